// round 10
// baseline (speedup 1.0000x reference)
#include <cuda_runtime.h>
#include <cuda_bf16.h>
#include <math.h>
#include <stdint.h>

#define B_   8
#define S_   512
#define HID_ 768
#define H_   12
#define D_   64
#define BS_  (B_*S_)          // 4096
#define BH_  (B_*H_)          // 96

#define CTX_ELEMS ((size_t)B_*S_*HID_)        // 3,145,728
#define SC_ELEMS  ((size_t)BH_*S_*S_)         // 25,165,824

#define HPAIRS ((size_t)BS_*HID_/2)           // 1,572,864
#define WPAIRS ((size_t)HID_*HID_/2)          //   294,912
#define ROWP   (HID_/2)                       // 384 pairs per row

// Scratch (device globals — no allocation in kernel_launch)
__device__ float g_q[BH_*S_*D_];
__device__ float g_k[BH_*S_*D_];
__device__ float g_v[BH_*S_*D_];
__device__ uint2 g_hidP[HPAIRS];              // (bf16x2 hi, bf16x2 lo) per k-pair
__device__ uint2 g_WP[3][WPAIRS];

__device__ __forceinline__ float to_tf32(float x) {
    float r;
    asm("cvt.rna.tf32.f32 %0, %1;" : "=f"(r) : "f"(x));
    return r;
}

__device__ __forceinline__ void mma_tf32(float* c, const uint32_t* a, const uint32_t* b) {
    asm volatile(
        "mma.sync.aligned.m16n8k8.row.col.f32.tf32.tf32.f32 "
        "{%0,%1,%2,%3}, {%4,%5,%6,%7}, {%8,%9}, {%0,%1,%2,%3};\n"
        : "+f"(c[0]), "+f"(c[1]), "+f"(c[2]), "+f"(c[3])
        : "r"(a[0]), "r"(a[1]), "r"(a[2]), "r"(a[3]), "r"(b[0]), "r"(b[1]));
}

__device__ __forceinline__ void mma_bf16(float* c, const uint32_t* a, const uint32_t* b) {
    asm volatile(
        "mma.sync.aligned.m16n8k16.row.col.f32.bf16.bf16.f32 "
        "{%0,%1,%2,%3}, {%4,%5,%6,%7}, {%8,%9}, {%0,%1,%2,%3};\n"
        : "+f"(c[0]), "+f"(c[1]), "+f"(c[2]), "+f"(c[3])
        : "r"(a[0]), "r"(a[1]), "r"(a[2]), "r"(a[3]), "r"(b[0]), "r"(b[1]));
}

__device__ __forceinline__ uint32_t smem_u32(const void* p) {
    return (uint32_t)__cvta_generic_to_shared(p);
}

__device__ __forceinline__ void cp16(uint32_t dst, const void* src) {
    asm volatile("cp.async.ca.shared.global [%0], [%1], 16;\n" :: "r"(dst), "l"(src));
}

// ---------------------------------------------------------------------------
// Kernel 0: split hid and W into 2-term bf16 (hi, lo) pair format. [R6 exact]
// ---------------------------------------------------------------------------
__global__ void __launch_bounds__(256)
split_prep(const float* __restrict__ hid, const float* __restrict__ Wq,
           const float* __restrict__ Wk,  const float* __restrict__ Wv)
{
    size_t i = (size_t)blockIdx.x * 256 + threadIdx.x;
    float2 v;
    uint2* dst;
    if (i < HPAIRS) {
        v = ((const float2*)hid)[i];
        dst = &g_hidP[i];
    } else {
        size_t j = i - HPAIRS;
        int w = (int)(j / WPAIRS);
        size_t o = j - (size_t)w * WPAIRS;
        const float* W = (w == 0) ? Wq : ((w == 1) ? Wk : Wv);
        v = ((const float2*)W)[o];
        dst = &g_WP[w][o];
    }
    __nv_bfloat162 h;
    h.x = __float2bfloat16_rn(v.x);
    h.y = __float2bfloat16_rn(v.y);
    float r0 = v.x - __bfloat162float(h.x);
    float r1 = v.y - __bfloat162float(h.y);
    __nv_bfloat162 l;
    l.x = __float2bfloat16_rn(r0);
    l.y = __float2bfloat16_rn(r1);
    uint2 o2;
    o2.x = *(uint32_t*)&h;
    o2.y = *(uint32_t*)&l;
    *dst = o2;
}

// ---------------------------------------------------------------------------
// Kernel 1: QKV projection via 2-term bf16 MMA. [R6 loop exact; tf32 epilogue
// validated bit-identical in R9]
// Block 128x128, BK=32, double-buffered. 8 warps (2m x 4n), warp 64x32.
// ---------------------------------------------------------------------------
__global__ void __launch_bounds__(256, 2)
qkv_mma(const float* __restrict__ bq, const float* __restrict__ bk,
        const float* __restrict__ bv)
{
    const int z = blockIdx.z;
    const uint2* Wp   = g_WP[z];
    const float* bias = (z == 0) ? bq : ((z == 1) ? bk : bv);
    float* out        = (z == 0) ? g_q : ((z == 1) ? g_k : g_v);

    const int m0 = blockIdx.y * 128;
    const int n0 = blockIdx.x * 128;

    __shared__ __align__(16) uint32_t As[2][128][40];
    __shared__ __align__(16) uint32_t Bs[2][128][40];

    const int tid  = threadIdx.x;
    const int lane = tid & 31;
    const int wid  = tid >> 5;
    const int gr   = lane >> 2;
    const int gc   = lane & 3;
    const int wm   = (wid & 1) * 64;
    const int wn   = (wid >> 1) * 32;

    float c[4][4][4];
    #pragma unroll
    for (int im = 0; im < 4; im++)
        #pragma unroll
        for (int jn = 0; jn < 4; jn++)
            #pragma unroll
            for (int r = 0; r < 4; r++) c[im][jn][r] = 0.0f;

    #define LOAD_STAGE(buf, kp0)                                                 \
    {                                                                            \
        _Pragma("unroll")                                                        \
        for (int r = 0; r < 4; r++) {                                            \
            int cc = tid + 256 * r; int row = cc >> 3; int sub = cc & 7;         \
            cp16(smem_u32(&As[buf][row][sub * 4]),                               \
                 g_hidP + (size_t)(m0 + row) * ROWP + (kp0) + sub * 2);          \
        }                                                                        \
        _Pragma("unroll")                                                        \
        for (int r = 0; r < 4; r++) {                                            \
            int cc = tid + 256 * r; int row = cc >> 3; int sub = cc & 7;         \
            cp16(smem_u32(&Bs[buf][row][sub * 4]),                               \
                 Wp + (size_t)(n0 + row) * ROWP + (kp0) + sub * 2);              \
        }                                                                        \
        asm volatile("cp.async.commit_group;\n");                                \
    }

    LOAD_STAGE(0, 0)

    const int NIT = HID_ / 32;   // 24 stages of k32
    for (int it = 0; it < NIT; it++) {
        asm volatile("cp.async.wait_group 0;\n");
        __syncthreads();
        if (it + 1 < NIT) { LOAD_STAGE((it + 1) & 1, (it + 1) * 16) }

        const int buf = it & 1;
        #pragma unroll
        for (int ks = 0; ks < 2; ks++) {
            const int c0 = 2 * gc + 16 * ks;
            uint32_t ahi[4][4], alo[4][4];
            #pragma unroll
            for (int im = 0; im < 4; im++) {
                int r = wm + im * 16 + gr;
                uint2 t;
                t = *(const uint2*)&As[buf][r    ][c0    ]; ahi[im][0] = t.x; alo[im][0] = t.y;
                t = *(const uint2*)&As[buf][r + 8][c0    ]; ahi[im][1] = t.x; alo[im][1] = t.y;
                t = *(const uint2*)&As[buf][r    ][c0 + 8]; ahi[im][2] = t.x; alo[im][2] = t.y;
                t = *(const uint2*)&As[buf][r + 8][c0 + 8]; ahi[im][3] = t.x; alo[im][3] = t.y;
            }
            #pragma unroll
            for (int jn = 0; jn < 4; jn++) {
                int n = wn + jn * 8 + gr;
                uint2 t0 = *(const uint2*)&Bs[buf][n][c0    ];
                uint2 t1 = *(const uint2*)&Bs[buf][n][c0 + 8];
                uint32_t bhi[2] = {t0.x, t1.x};
                uint32_t blo[2] = {t0.y, t1.y};
                #pragma unroll
                for (int im = 0; im < 4; im++) {
                    mma_bf16(c[im][jn], ahi[im], bhi);
                    mma_bf16(c[im][jn], ahi[im], blo);
                    mma_bf16(c[im][jn], alo[im], bhi);
                }
            }
        }
        __syncthreads();
    }
    #undef LOAD_STAGE

    // Epilogue: + bias, round to tf32 (bit-identical to consumer-side cvt).
    const int h      = (n0 + wn) >> 6;
    const int d_base = (n0 + wn) & 63;
    #pragma unroll
    for (int jn = 0; jn < 4; jn++) {
        int d = d_base + jn * 8 + gc * 2;
        float b0 = bias[n0 + wn + jn * 8 + gc * 2];
        float b1 = bias[n0 + wn + jn * 8 + gc * 2 + 1];
        #pragma unroll
        for (int im = 0; im < 4; im++) {
            int m = m0 + wm + im * 16 + gr;
            int b = m >> 9;
            int s = m & 511;
            float* o = out + (((size_t)(b * H_ + h) * S_ + s) * D_ + d);
            *(float2*)o            = make_float2(to_tf32(c[im][jn][0] + b0),
                                                 to_tf32(c[im][jn][1] + b1));
            *(float2*)(o + 8 * D_) = make_float2(to_tf32(c[im][jn][2] + b0),
                                                 to_tf32(c[im][jn][3] + b1));
        }
    }
}

// ---------------------------------------------------------------------------
// Kernel 2: symmetric self-similarity scores (qq, kk, vv). [R8 internals,
// correctness-validated] Upper-triangle 64x64 block pairs (36 of 64);
// off-diagonal tiles written twice (direct + smem-staged transpose).
// 128 threads (4 warps 2x2). grid: (36, 1, 3*96).
// ---------------------------------------------------------------------------
__global__ void __launch_bounds__(128)
scores_sym(const float* __restrict__ mask, float* __restrict__ out_base)
{
    const int z    = blockIdx.z;
    const int type = 1 + z / BH_;       // 1:qq 2:kk 3:vv
    const int bh   = z % BH_;

    const float* X = (type == 1) ? g_q : ((type == 2) ? g_k : g_v);
    X += (size_t)bh * S_ * D_;

    float* out = out_base + (size_t)type * SC_ELEMS + (size_t)bh * S_ * S_;
    const float* mrow = mask + (size_t)(bh / H_) * S_;

    // decode upper-triangle pair (i <= j) from linear index
    int t = blockIdx.x, bi = 0;
    while (t >= 8 - bi) { t -= 8 - bi; bi++; }
    const int bj = bi + t;
    const int m0 = bi * 64;
    const int n0 = bj * 64;

    __shared__ float Xs[64][68];
    __shared__ float Ys[64][68];
    __shared__ float Cs[64][68];

    const int tid = threadIdx.x;

    #pragma unroll
    for (int r = 0; r < 8; r++) {
        int idx = tid + 128 * r;
        int row = idx >> 4;
        int q   = idx & 15;
        *(float4*)&Xs[row][q * 4] = *(const float4*)(X + (size_t)(m0 + row) * D_ + q * 4);
        *(float4*)&Ys[row][q * 4] = *(const float4*)(X + (size_t)(n0 + row) * D_ + q * 4);
    }
    __syncthreads();

    const int lane = tid & 31;
    const int wid  = tid >> 5;
    const int wm   = (wid & 1) * 32;
    const int wn   = (wid >> 1) * 32;
    const int gr   = lane >> 2;
    const int gc   = lane & 3;

    float c[2][4][4];
    #pragma unroll
    for (int im = 0; im < 2; im++)
        #pragma unroll
        for (int jn = 0; jn < 4; jn++)
            #pragma unroll
            for (int r = 0; r < 4; r++) c[im][jn][r] = 0.0f;

    #pragma unroll
    for (int k0 = 0; k0 < 64; k0 += 8) {
        uint32_t a[2][4], b[4][2];
        #pragma unroll
        for (int im = 0; im < 2; im++) {
            int r0 = wm + im * 16 + gr;
            a[im][0] = __float_as_uint(Xs[r0    ][k0 + gc    ]);
            a[im][1] = __float_as_uint(Xs[r0 + 8][k0 + gc    ]);
            a[im][2] = __float_as_uint(Xs[r0    ][k0 + gc + 4]);
            a[im][3] = __float_as_uint(Xs[r0 + 8][k0 + gc + 4]);
        }
        #pragma unroll
        for (int jn = 0; jn < 4; jn++) {
            int n = wn + jn * 8 + gr;
            b[jn][0] = __float_as_uint(Ys[n][k0 + gc    ]);
            b[jn][1] = __float_as_uint(Ys[n][k0 + gc + 4]);
        }
        #pragma unroll
        for (int im = 0; im < 2; im++)
            #pragma unroll
            for (int jn = 0; jn < 4; jn++)
                mma_tf32(c[im][jn], a[im], b[jn]);
    }

    // write direct tile (+ stage scaled dot for transpose)
    #pragma unroll
    for (int im = 0; im < 2; im++) {
        #pragma unroll
        for (int jn = 0; jn < 4; jn++) {
            int rl = wm + im * 16 + gr;
            int cl = wn + jn * 8 + gc * 2;
            float d00 = c[im][jn][0] * 0.125f, d01 = c[im][jn][1] * 0.125f;
            float d10 = c[im][jn][2] * 0.125f, d11 = c[im][jn][3] * 0.125f;
            float mv0 = mrow[n0 + cl], mv1 = mrow[n0 + cl + 1];
            *(float2*)(out + (size_t)(m0 + rl)     * S_ + n0 + cl) = make_float2(d00 + mv0, d01 + mv1);
            *(float2*)(out + (size_t)(m0 + rl + 8) * S_ + n0 + cl) = make_float2(d10 + mv0, d11 + mv1);
            Cs[rl    ][cl] = d00;  Cs[rl    ][cl + 1] = d01;
            Cs[rl + 8][cl] = d10;  Cs[rl + 8][cl + 1] = d11;
        }
    }

    if (bi != bj) {
        __syncthreads();
        // transposed tile at block (bj, bi): T[r'][c'] = C[c'][r'] + mask[m0+c']
        const int r2   = tid >> 1;           // 0..63
        const int half = (tid & 1) * 32;
        float* orow = out + (size_t)(n0 + r2) * S_ + m0 + half;
        #pragma unroll
        for (int q = 0; q < 8; q++) {
            int cb = half + q * 4;
            float4 v = make_float4(Cs[cb    ][r2] + mrow[m0 + cb    ],
                                   Cs[cb + 1][r2] + mrow[m0 + cb + 1],
                                   Cs[cb + 2][r2] + mrow[m0 + cb + 2],
                                   Cs[cb + 3][r2] + mrow[m0 + cb + 3]);
            *(float4*)(orow + q * 4) = v;
        }
    }
}

// ---------------------------------------------------------------------------
// Kernel 3: fused qk-scores + softmax + P@V, all-MMA (tf32). [R6 internals,
// cvt-free loads (inputs pre-rounded to tf32) — validated in R9]
// 128 threads = 4 warps; warp w owns rows [16w,16w+16). grid: (8, 96).
// ---------------------------------------------------------------------------
__global__ void __launch_bounds__(128)
flash_attn(const float* __restrict__ mask, float* __restrict__ sout_base,
           float* __restrict__ ctx)
{
    const int bh = blockIdx.y;
    const int q0 = blockIdx.x * 64;
    const int b  = bh / H_;
    const int h  = bh - b * H_;
    const float* Qp = g_q + (size_t)bh * S_ * D_;
    const float* Kp = g_k + (size_t)bh * S_ * D_;
    const float* Vp = g_v + (size_t)bh * S_ * D_;
    float* sout = sout_base + (size_t)bh * S_ * S_;
    const float* mrow = mask + (size_t)b * S_;

    __shared__ float QPs[64][68];
    __shared__ float Ks[64][68];
    __shared__ float Vs[64][72];

    const int tid  = threadIdx.x;
    const int lane = tid & 31;
    const int w    = tid >> 5;
    const int gr   = lane >> 2;
    const int gc   = lane & 3;

    #pragma unroll
    for (int r = 0; r < 8; r++) {
        int idx = tid + 128 * r;
        int row = idx >> 4;
        int q   = idx & 15;
        *(float4*)&QPs[row][q * 4] =
            *(const float4*)(Qp + (size_t)(q0 + row) * D_ + q * 4);
    }
    __syncthreads();

    uint32_t aq[8][4];
    #pragma unroll
    for (int ks = 0; ks < 8; ks++) {
        int r0 = w * 16 + gr;
        aq[ks][0] = __float_as_uint(QPs[r0    ][8*ks + gc    ]);
        aq[ks][1] = __float_as_uint(QPs[r0 + 8][8*ks + gc    ]);
        aq[ks][2] = __float_as_uint(QPs[r0    ][8*ks + gc + 4]);
        aq[ks][3] = __float_as_uint(QPs[r0 + 8][8*ks + gc + 4]);
    }

    float o[8][4];
    #pragma unroll
    for (int jd = 0; jd < 8; jd++)
        #pragma unroll
        for (int r = 0; r < 4; r++) o[jd][r] = 0.0f;

    float m0 = -1e30f, m1 = -1e30f, l0 = 0.0f, l1 = 0.0f;
    const int rowg = q0 + w * 16 + gr;

    for (int kt = 0; kt < 8; kt++) {
        #pragma unroll
        for (int r = 0; r < 8; r++) {
            int idx = tid + 128 * r;
            int row = idx >> 4;
            int q   = idx & 15;
            *(float4*)&Ks[row][q * 4] =
                *(const float4*)(Kp + (size_t)(kt*64 + row) * D_ + q * 4);
            *(float4*)&Vs[row][q * 4] =
                *(const float4*)(Vp + (size_t)(kt*64 + row) * D_ + q * 4);
        }
        __syncthreads();

        float s[8][4];
        #pragma unroll
        for (int jn = 0; jn < 8; jn++) {
            #pragma unroll
            for (int r = 0; r < 4; r++) s[jn][r] = 0.0f;
            #pragma unroll
            for (int ks = 0; ks < 8; ks++) {
                uint32_t bv[2];
                bv[0] = __float_as_uint(Ks[jn*8 + gr][8*ks + gc    ]);
                bv[1] = __float_as_uint(Ks[jn*8 + gr][8*ks + gc + 4]);
                mma_tf32(s[jn], aq[ks], bv);
            }
        }

        float mx0 = -1e30f, mx1 = -1e30f;
        #pragma unroll
        for (int jn = 0; jn < 8; jn++) {
            int col = kt*64 + jn*8 + gc*2;
            float mv0 = mrow[col], mv1 = mrow[col + 1];
            s[jn][0] = s[jn][0]*0.125f + mv0;  s[jn][1] = s[jn][1]*0.125f + mv1;
            s[jn][2] = s[jn][2]*0.125f + mv0;  s[jn][3] = s[jn][3]*0.125f + mv1;
            *(float2*)(sout + (size_t)rowg       * S_ + col) = make_float2(s[jn][0], s[jn][1]);
            *(float2*)(sout + (size_t)(rowg + 8) * S_ + col) = make_float2(s[jn][2], s[jn][3]);
            mx0 = fmaxf(mx0, fmaxf(s[jn][0], s[jn][1]));
            mx1 = fmaxf(mx1, fmaxf(s[jn][2], s[jn][3]));
        }
        mx0 = fmaxf(mx0, __shfl_xor_sync(0xffffffffu, mx0, 1));
        mx0 = fmaxf(mx0, __shfl_xor_sync(0xffffffffu, mx0, 2));
        mx1 = fmaxf(mx1, __shfl_xor_sync(0xffffffffu, mx1, 1));
        mx1 = fmaxf(mx1, __shfl_xor_sync(0xffffffffu, mx1, 2));

        float mn0 = fmaxf(m0, mx0), mn1 = fmaxf(m1, mx1);
        float sc0 = __expf(m0 - mn0), sc1 = __expf(m1 - mn1);

        float ps0 = 0.0f, ps1 = 0.0f;
        #pragma unroll
        for (int jn = 0; jn < 8; jn++) {
            float p0 = __expf(s[jn][0] - mn0), p1 = __expf(s[jn][1] - mn0);
            float p2 = __expf(s[jn][2] - mn1), p3 = __expf(s[jn][3] - mn1);
            ps0 += p0 + p1;  ps1 += p2 + p3;
            int col = jn*8 + gc*2;
            int r0  = w*16 + gr;
            *(float2*)&QPs[r0    ][col] = make_float2(to_tf32(p0), to_tf32(p1));
            *(float2*)&QPs[r0 + 8][col] = make_float2(to_tf32(p2), to_tf32(p3));
        }
        ps0 += __shfl_xor_sync(0xffffffffu, ps0, 1);
        ps0 += __shfl_xor_sync(0xffffffffu, ps0, 2);
        ps1 += __shfl_xor_sync(0xffffffffu, ps1, 1);
        ps1 += __shfl_xor_sync(0xffffffffu, ps1, 2);
        l0 = l0 * sc0 + ps0;  l1 = l1 * sc1 + ps1;
        m0 = mn0;  m1 = mn1;

        #pragma unroll
        for (int jd = 0; jd < 8; jd++) {
            o[jd][0] *= sc0;  o[jd][1] *= sc0;
            o[jd][2] *= sc1;  o[jd][3] *= sc1;
        }
        __syncwarp();

        #pragma unroll
        for (int ks = 0; ks < 8; ks++) {
            uint32_t ap[4];
            int r0 = w*16 + gr;
            ap[0] = __float_as_uint(QPs[r0    ][8*ks + gc    ]);
            ap[1] = __float_as_uint(QPs[r0 + 8][8*ks + gc    ]);
            ap[2] = __float_as_uint(QPs[r0    ][8*ks + gc + 4]);
            ap[3] = __float_as_uint(QPs[r0 + 8][8*ks + gc + 4]);
            #pragma unroll
            for (int jd = 0; jd < 8; jd++) {
                uint32_t bv[2];
                bv[0] = __float_as_uint(Vs[8*ks + gc    ][jd*8 + gr]);
                bv[1] = __float_as_uint(Vs[8*ks + gc + 4][jd*8 + gr]);
                mma_tf32(o[jd], ap, bv);
            }
        }
        __syncthreads();
    }

    float i0 = 1.0f / l0, i1 = 1.0f / l1;
    #pragma unroll
    for (int jd = 0; jd < 8; jd++) {
        int d = jd*8 + gc*2;
        float* op = ctx + ((size_t)(b * S_ + rowg) * HID_ + h * D_ + d);
        *(float2*)op              = make_float2(o[jd][0] * i0, o[jd][1] * i0);
        *(float2*)(op + 8 * HID_) = make_float2(o[jd][2] * i1, o[jd][3] * i1);
    }
}

// ---------------------------------------------------------------------------
extern "C" void kernel_launch(void* const* d_in, const int* in_sizes, int n_in,
                              void* d_out, int out_size)
{
    const float* hid  = (const float*)d_in[0];
    const float* mask = (const float*)d_in[1];
    const float* Wq   = (const float*)d_in[2];
    const float* bq   = (const float*)d_in[3];
    const float* Wk   = (const float*)d_in[4];
    const float* bk   = (const float*)d_in[5];
    const float* Wv   = (const float*)d_in[6];
    const float* bv   = (const float*)d_in[7];
    float* out = (float*)d_out;

    // 0) split hid/W into bf16 (hi,lo) pair format
    const int nprep = (int)((HPAIRS + 3 * WPAIRS) / 256);   // 9600
    split_prep<<<nprep, 256>>>(hid, Wq, Wk, Wv);

    // 1) Q,K,V projections (2-term bf16 MMA, tf32-rounded outputs)
    qkv_mma<<<dim3(HID_ / 128, BS_ / 128, 3), 256>>>(bq, bk, bv);

    // 2) qq / kk / vv self-similarity scores (symmetric: 36 block-pairs)
    scores_sym<<<dim3(36, 1, 3 * BH_), 128>>>(mask, out + CTX_ELEMS);

    // 3) fused qk scores + softmax + P@V -> scores(qk) region + ctx
    flash_attn<<<dim3(S_ / 64, BH_), 128>>>(mask, out + CTX_ELEMS, out);
}

// round 11
// speedup vs baseline: 1.3029x; 1.3029x over previous
#include <cuda_runtime.h>
#include <cuda_fp16.h>
#include <math.h>
#include <stdint.h>

#define B_   8
#define S_   512
#define HID_ 768
#define H_   12
#define D_   64
#define BS_  (B_*S_)          // 4096
#define BH_  (B_*H_)          // 96

#define CTX_ELEMS ((size_t)B_*S_*HID_)        // 3,145,728
#define SC_ELEMS  ((size_t)BH_*S_*S_)         // 25,165,824

#define NHID ((size_t)BS_*HID_)               // 3,145,728
#define NW   ((size_t)HID_*HID_)              //   589,824
#define ROWP (HID_/2)                         // 384 pairs per W row

// Scratch (device globals — no allocation in kernel_launch)
__device__ float g_q[BH_*S_*D_];
__device__ float g_k[BH_*S_*D_];
__device__ float g_v[BH_*S_*D_];
__device__ __half g_hidH[NHID];               // hidden: fp16 hi plane only
__device__ uint2  g_WPf[3][NW/2];             // W: (f16x2 hi, f16x2 lo) per pair

__device__ __forceinline__ float to_tf32(float x) {
    float r;
    asm("cvt.rna.tf32.f32 %0, %1;" : "=f"(r) : "f"(x));
    return r;
}

__device__ __forceinline__ void mma_tf32(float* c, const uint32_t* a, const uint32_t* b) {
    asm volatile(
        "mma.sync.aligned.m16n8k8.row.col.f32.tf32.tf32.f32 "
        "{%0,%1,%2,%3}, {%4,%5,%6,%7}, {%8,%9}, {%0,%1,%2,%3};\n"
        : "+f"(c[0]), "+f"(c[1]), "+f"(c[2]), "+f"(c[3])
        : "r"(a[0]), "r"(a[1]), "r"(a[2]), "r"(a[3]), "r"(b[0]), "r"(b[1]));
}

__device__ __forceinline__ void mma_f16(float* c, const uint32_t* a, const uint32_t* b) {
    asm volatile(
        "mma.sync.aligned.m16n8k16.row.col.f32.f16.f16.f32 "
        "{%0,%1,%2,%3}, {%4,%5,%6,%7}, {%8,%9}, {%0,%1,%2,%3};\n"
        : "+f"(c[0]), "+f"(c[1]), "+f"(c[2]), "+f"(c[3])
        : "r"(a[0]), "r"(a[1]), "r"(a[2]), "r"(a[3]), "r"(b[0]), "r"(b[1]));
}

__device__ __forceinline__ uint32_t smem_u32(const void* p) {
    return (uint32_t)__cvta_generic_to_shared(p);
}

__device__ __forceinline__ void cp16(uint32_t dst, const void* src) {
    asm volatile("cp.async.ca.shared.global [%0], [%1], 16;\n" :: "r"(dst), "l"(src));
}

// ---------------------------------------------------------------------------
// Kernel 0: prep. hidden -> fp16 hi plane; W -> fp16 (hi,lo) pair format.
// ---------------------------------------------------------------------------
#define A_THREADS (NHID / 8)                  // 393,216
#define W_THREADS (3 * NW / 8)                // 221,184
#define PREP_BLOCKS (int)((A_THREADS + W_THREADS) / 256)   // 2400

__global__ void __launch_bounds__(256)
split_prep(const float* __restrict__ hid, const float* __restrict__ Wq,
           const float* __restrict__ Wk,  const float* __restrict__ Wv)
{
    size_t i = (size_t)blockIdx.x * 256 + threadIdx.x;
    if (i < A_THREADS) {
        size_t base = i * 8;
        float4 v0 = *(const float4*)(hid + base);
        float4 v1 = *(const float4*)(hid + base + 4);
        __half2 o[4];
        o[0] = __half2(__float2half_rn(v0.x), __float2half_rn(v0.y));
        o[1] = __half2(__float2half_rn(v0.z), __float2half_rn(v0.w));
        o[2] = __half2(__float2half_rn(v1.x), __float2half_rn(v1.y));
        o[3] = __half2(__float2half_rn(v1.z), __float2half_rn(v1.w));
        *(uint4*)(g_hidH + base) = *(uint4*)o;
    } else {
        size_t j = i - A_THREADS;
        int w = (int)(j / (NW / 8));
        size_t o8 = (j - (size_t)w * (NW / 8)) * 8;
        const float* W = (w == 0) ? Wq : ((w == 1) ? Wk : Wv);
        float4 v0 = *(const float4*)(W + o8);
        float4 v1 = *(const float4*)(W + o8 + 4);
        float f[8] = {v0.x, v0.y, v0.z, v0.w, v1.x, v1.y, v1.z, v1.w};
        uint2 p[4];
        #pragma unroll
        for (int q = 0; q < 4; q++) {
            __half h0 = __float2half_rn(f[2*q]);
            __half h1 = __float2half_rn(f[2*q+1]);
            __half2 hh = __half2(h0, h1);
            __half2 ll = __half2(__float2half_rn(f[2*q]   - __half2float(h0)),
                                 __float2half_rn(f[2*q+1] - __half2float(h1)));
            p[q].x = *(uint32_t*)&hh;
            p[q].y = *(uint32_t*)&ll;
        }
        uint2* dst = g_WPf[w] + o8 / 2;
        *(uint4*)dst       = *(uint4*)&p[0];
        *(uint4*)(dst + 2) = *(uint4*)&p[2];
    }
}

// ---------------------------------------------------------------------------
// Kernel 1: QKV projection via fp16 2-term MMA: C = Ah*Bh + Ah*Bl (al*b
// dropped; error ~2^-11 incoherent over K=768 -> ~3.5e-4, within budget).
// Block 128x128, BK=32, double-buffered cp.async. 8 warps (2m x 4n), warp 64x32.
// A smem halves vs bf16 version -> crossbar bytes 2/3, MMA count 2/3.
// ---------------------------------------------------------------------------
__global__ void __launch_bounds__(256, 2)
qkv_mma(const float* __restrict__ bq, const float* __restrict__ bk,
        const float* __restrict__ bv)
{
    const int z = blockIdx.z;
    const uint2* Wp   = g_WPf[z];
    const float* bias = (z == 0) ? bq : ((z == 1) ? bk : bv);
    float* out        = (z == 0) ? g_q : ((z == 1) ? g_k : g_v);

    const int m0 = blockIdx.y * 128;
    const int n0 = blockIdx.x * 128;

    __shared__ __align__(16) uint32_t As[2][128][20];   // f16x2 words, 16 used
    __shared__ __align__(16) uint32_t Bs[2][128][40];   // (hi,lo) pairs, 32 used

    const int tid  = threadIdx.x;
    const int lane = tid & 31;
    const int wid  = tid >> 5;
    const int gr   = lane >> 2;
    const int gc   = lane & 3;
    const int wm   = (wid & 1) * 64;
    const int wn   = (wid >> 1) * 32;

    float c[4][4][4];
    #pragma unroll
    for (int im = 0; im < 4; im++)
        #pragma unroll
        for (int jn = 0; jn < 4; jn++)
            #pragma unroll
            for (int r = 0; r < 4; r++) c[im][jn][r] = 0.0f;

    // stage = k32: A row 64B (4 chunks), B row 128B (8 chunks)
    #define LOAD_STAGE(buf, it_)                                                 \
    {                                                                            \
        _Pragma("unroll")                                                        \
        for (int r = 0; r < 2; r++) {                                            \
            int cc = tid + 256 * r; int row = cc >> 2; int sub = cc & 3;         \
            cp16(smem_u32(&As[buf][row][sub * 4]),                               \
                 g_hidH + (size_t)(m0 + row) * HID_ + (it_) * 32 + sub * 8);     \
        }                                                                        \
        _Pragma("unroll")                                                        \
        for (int r = 0; r < 4; r++) {                                            \
            int cc = tid + 256 * r; int row = cc >> 3; int sub = cc & 7;         \
            cp16(smem_u32(&Bs[buf][row][sub * 4]),                               \
                 Wp + (size_t)(n0 + row) * ROWP + (it_) * 16 + sub * 2);         \
        }                                                                        \
        asm volatile("cp.async.commit_group;\n");                                \
    }

    LOAD_STAGE(0, 0)

    const int NIT = HID_ / 32;   // 24 stages of k32
    for (int it = 0; it < NIT; it++) {
        asm volatile("cp.async.wait_group 0;\n");
        __syncthreads();
        if (it + 1 < NIT) { LOAD_STAGE((it + 1) & 1, it + 1) }

        const int buf = it & 1;
        #pragma unroll
        for (int ks = 0; ks < 2; ks++) {       // two k16 steps per stage
            const int acol = 8 * ks + gc;
            const int c0   = 16 * ks + 2 * gc;
            uint32_t a[4][4], bhi[4][2], blo[4][2];
            #pragma unroll
            for (int im = 0; im < 4; im++) {
                int r = wm + im * 16 + gr;
                a[im][0] = As[buf][r    ][acol    ];
                a[im][1] = As[buf][r + 8][acol    ];
                a[im][2] = As[buf][r    ][acol + 4];
                a[im][3] = As[buf][r + 8][acol + 4];
            }
            #pragma unroll
            for (int jn = 0; jn < 4; jn++) {
                int n = wn + jn * 8 + gr;
                uint2 t0 = *(const uint2*)&Bs[buf][n][c0    ];
                uint2 t1 = *(const uint2*)&Bs[buf][n][c0 + 8];
                bhi[jn][0] = t0.x; bhi[jn][1] = t1.x;
                blo[jn][0] = t0.y; blo[jn][1] = t1.y;
            }
            // term hh (16 independent MMAs), then term hl
            #pragma unroll
            for (int im = 0; im < 4; im++)
                #pragma unroll
                for (int jn = 0; jn < 4; jn++)
                    mma_f16(c[im][jn], a[im], bhi[jn]);
            #pragma unroll
            for (int im = 0; im < 4; im++)
                #pragma unroll
                for (int jn = 0; jn < 4; jn++)
                    mma_f16(c[im][jn], a[im], blo[jn]);
        }
        __syncthreads();
    }
    #undef LOAD_STAGE

    // Epilogue: + bias, round to tf32 (consumers are cvt-free).
    const int h      = (n0 + wn) >> 6;
    const int d_base = (n0 + wn) & 63;
    #pragma unroll
    for (int jn = 0; jn < 4; jn++) {
        int d = d_base + jn * 8 + gc * 2;
        float b0 = bias[n0 + wn + jn * 8 + gc * 2];
        float b1 = bias[n0 + wn + jn * 8 + gc * 2 + 1];
        #pragma unroll
        for (int im = 0; im < 4; im++) {
            int m = m0 + wm + im * 16 + gr;
            int b = m >> 9;
            int s = m & 511;
            float* o = out + (((size_t)(b * H_ + h) * S_ + s) * D_ + d);
            *(float2*)o            = make_float2(to_tf32(c[im][jn][0] + b0),
                                                 to_tf32(c[im][jn][1] + b1));
            *(float2*)(o + 8 * D_) = make_float2(to_tf32(c[im][jn][2] + b0),
                                                 to_tf32(c[im][jn][3] + b1));
        }
    }
}

// ---------------------------------------------------------------------------
// Kernel 2: self-similarity scores (qq, kk, vv) via tf32 mma. [R6 validated,
// cvt-free loads — inputs pre-rounded to tf32]
// Block: 64(q) x 128(k), 256 threads (8 warps 2x4). grid: (4, 8, 3*96).
// ---------------------------------------------------------------------------
__global__ void __launch_bounds__(256)
scores_sim(const float* __restrict__ mask, float* __restrict__ out_base)
{
    const int z    = blockIdx.z;
    const int type = 1 + z / BH_;       // 1:qq 2:kk 3:vv
    const int bh   = z % BH_;

    const float* X = (type == 1) ? g_q : ((type == 2) ? g_k : g_v);
    X += (size_t)bh * S_ * D_;

    float* out = out_base + (size_t)type * SC_ELEMS + (size_t)bh * S_ * S_;
    const float* mrow = mask + (size_t)(bh / H_) * S_;

    const int m0 = blockIdx.y * 64;
    const int n0 = blockIdx.x * 128;

    __shared__ float Xs[64][68];
    __shared__ float Ys[128][68];

    const int tid = threadIdx.x;

    #pragma unroll
    for (int r = 0; r < 4; r++) {
        int idx = tid + 256 * r;
        int row = idx >> 4;
        int q   = idx & 15;
        *(float4*)&Xs[row][q * 4] = *(const float4*)(X + (size_t)(m0 + row) * D_ + q * 4);
    }
    #pragma unroll
    for (int r = 0; r < 8; r++) {
        int idx = tid + 256 * r;
        int row = idx >> 4;
        int q   = idx & 15;
        *(float4*)&Ys[row][q * 4] = *(const float4*)(X + (size_t)(n0 + row) * D_ + q * 4);
    }
    __syncthreads();

    const int lane = tid & 31;
    const int wid  = tid >> 5;
    const int wm   = (wid & 1) * 32;
    const int wn   = (wid >> 1) * 32;
    const int gr   = lane >> 2;
    const int gc   = lane & 3;

    float c[2][4][4];
    #pragma unroll
    for (int im = 0; im < 2; im++)
        #pragma unroll
        for (int jn = 0; jn < 4; jn++)
            #pragma unroll
            for (int r = 0; r < 4; r++) c[im][jn][r] = 0.0f;

    #pragma unroll
    for (int k0 = 0; k0 < 64; k0 += 8) {
        uint32_t a[2][4], b[4][2];
        #pragma unroll
        for (int im = 0; im < 2; im++) {
            int r0 = wm + im * 16 + gr;
            a[im][0] = __float_as_uint(Xs[r0    ][k0 + gc    ]);
            a[im][1] = __float_as_uint(Xs[r0 + 8][k0 + gc    ]);
            a[im][2] = __float_as_uint(Xs[r0    ][k0 + gc + 4]);
            a[im][3] = __float_as_uint(Xs[r0 + 8][k0 + gc + 4]);
        }
        #pragma unroll
        for (int jn = 0; jn < 4; jn++) {
            int n = wn + jn * 8 + gr;
            b[jn][0] = __float_as_uint(Ys[n][k0 + gc    ]);
            b[jn][1] = __float_as_uint(Ys[n][k0 + gc + 4]);
        }
        #pragma unroll
        for (int im = 0; im < 2; im++)
            #pragma unroll
            for (int jn = 0; jn < 4; jn++)
                mma_tf32(c[im][jn], a[im], b[jn]);
    }

    #pragma unroll
    for (int im = 0; im < 2; im++) {
        #pragma unroll
        for (int jn = 0; jn < 4; jn++) {
            int row = m0 + wm + im * 16 + gr;
            int col = n0 + wn + jn * 8 + gc * 2;
            float mv0 = mrow[col], mv1 = mrow[col + 1];
            float2 o0 = make_float2(c[im][jn][0] * 0.125f + mv0,
                                    c[im][jn][1] * 0.125f + mv1);
            float2 o1 = make_float2(c[im][jn][2] * 0.125f + mv0,
                                    c[im][jn][3] * 0.125f + mv1);
            *(float2*)(out + (size_t)row * S_ + col)       = o0;
            *(float2*)(out + (size_t)(row + 8) * S_ + col) = o1;
        }
    }
}

// ---------------------------------------------------------------------------
// Kernel 3: fused qk-scores + softmax + P@V, all-MMA (tf32). [R6 validated,
// cvt-free loads] 128 threads = 4 warps. grid: (8, 96).
// ---------------------------------------------------------------------------
__global__ void __launch_bounds__(128)
flash_attn(const float* __restrict__ mask, float* __restrict__ sout_base,
           float* __restrict__ ctx)
{
    const int bh = blockIdx.y;
    const int q0 = blockIdx.x * 64;
    const int b  = bh / H_;
    const int h  = bh - b * H_;
    const float* Qp = g_q + (size_t)bh * S_ * D_;
    const float* Kp = g_k + (size_t)bh * S_ * D_;
    const float* Vp = g_v + (size_t)bh * S_ * D_;
    float* sout = sout_base + (size_t)bh * S_ * S_;
    const float* mrow = mask + (size_t)b * S_;

    __shared__ float QPs[64][68];
    __shared__ float Ks[64][68];
    __shared__ float Vs[64][72];

    const int tid  = threadIdx.x;
    const int lane = tid & 31;
    const int w    = tid >> 5;
    const int gr   = lane >> 2;
    const int gc   = lane & 3;

    #pragma unroll
    for (int r = 0; r < 8; r++) {
        int idx = tid + 128 * r;
        int row = idx >> 4;
        int q   = idx & 15;
        *(float4*)&QPs[row][q * 4] =
            *(const float4*)(Qp + (size_t)(q0 + row) * D_ + q * 4);
    }
    __syncthreads();

    uint32_t aq[8][4];
    #pragma unroll
    for (int ks = 0; ks < 8; ks++) {
        int r0 = w * 16 + gr;
        aq[ks][0] = __float_as_uint(QPs[r0    ][8*ks + gc    ]);
        aq[ks][1] = __float_as_uint(QPs[r0 + 8][8*ks + gc    ]);
        aq[ks][2] = __float_as_uint(QPs[r0    ][8*ks + gc + 4]);
        aq[ks][3] = __float_as_uint(QPs[r0 + 8][8*ks + gc + 4]);
    }

    float o[8][4];
    #pragma unroll
    for (int jd = 0; jd < 8; jd++)
        #pragma unroll
        for (int r = 0; r < 4; r++) o[jd][r] = 0.0f;

    float m0 = -1e30f, m1 = -1e30f, l0 = 0.0f, l1 = 0.0f;
    const int rowg = q0 + w * 16 + gr;

    for (int kt = 0; kt < 8; kt++) {
        #pragma unroll
        for (int r = 0; r < 8; r++) {
            int idx = tid + 128 * r;
            int row = idx >> 4;
            int q   = idx & 15;
            *(float4*)&Ks[row][q * 4] =
                *(const float4*)(Kp + (size_t)(kt*64 + row) * D_ + q * 4);
            *(float4*)&Vs[row][q * 4] =
                *(const float4*)(Vp + (size_t)(kt*64 + row) * D_ + q * 4);
        }
        __syncthreads();

        float s[8][4];
        #pragma unroll
        for (int jn = 0; jn < 8; jn++) {
            #pragma unroll
            for (int r = 0; r < 4; r++) s[jn][r] = 0.0f;
            #pragma unroll
            for (int ks = 0; ks < 8; ks++) {
                uint32_t bv[2];
                bv[0] = __float_as_uint(Ks[jn*8 + gr][8*ks + gc    ]);
                bv[1] = __float_as_uint(Ks[jn*8 + gr][8*ks + gc + 4]);
                mma_tf32(s[jn], aq[ks], bv);
            }
        }

        float mx0 = -1e30f, mx1 = -1e30f;
        #pragma unroll
        for (int jn = 0; jn < 8; jn++) {
            int col = kt*64 + jn*8 + gc*2;
            float mv0 = mrow[col], mv1 = mrow[col + 1];
            s[jn][0] = s[jn][0]*0.125f + mv0;  s[jn][1] = s[jn][1]*0.125f + mv1;
            s[jn][2] = s[jn][2]*0.125f + mv0;  s[jn][3] = s[jn][3]*0.125f + mv1;
            *(float2*)(sout + (size_t)rowg       * S_ + col) = make_float2(s[jn][0], s[jn][1]);
            *(float2*)(sout + (size_t)(rowg + 8) * S_ + col) = make_float2(s[jn][2], s[jn][3]);
            mx0 = fmaxf(mx0, fmaxf(s[jn][0], s[jn][1]));
            mx1 = fmaxf(mx1, fmaxf(s[jn][2], s[jn][3]));
        }
        mx0 = fmaxf(mx0, __shfl_xor_sync(0xffffffffu, mx0, 1));
        mx0 = fmaxf(mx0, __shfl_xor_sync(0xffffffffu, mx0, 2));
        mx1 = fmaxf(mx1, __shfl_xor_sync(0xffffffffu, mx1, 1));
        mx1 = fmaxf(mx1, __shfl_xor_sync(0xffffffffu, mx1, 2));

        float mn0 = fmaxf(m0, mx0), mn1 = fmaxf(m1, mx1);
        float sc0 = __expf(m0 - mn0), sc1 = __expf(m1 - mn1);

        float ps0 = 0.0f, ps1 = 0.0f;
        #pragma unroll
        for (int jn = 0; jn < 8; jn++) {
            float p0 = __expf(s[jn][0] - mn0), p1 = __expf(s[jn][1] - mn0);
            float p2 = __expf(s[jn][2] - mn1), p3 = __expf(s[jn][3] - mn1);
            ps0 += p0 + p1;  ps1 += p2 + p3;
            int col = jn*8 + gc*2;
            int r0  = w*16 + gr;
            *(float2*)&QPs[r0    ][col] = make_float2(to_tf32(p0), to_tf32(p1));
            *(float2*)&QPs[r0 + 8][col] = make_float2(to_tf32(p2), to_tf32(p3));
        }
        ps0 += __shfl_xor_sync(0xffffffffu, ps0, 1);
        ps0 += __shfl_xor_sync(0xffffffffu, ps0, 2);
        ps1 += __shfl_xor_sync(0xffffffffu, ps1, 1);
        ps1 += __shfl_xor_sync(0xffffffffu, ps1, 2);
        l0 = l0 * sc0 + ps0;  l1 = l1 * sc1 + ps1;
        m0 = mn0;  m1 = mn1;

        #pragma unroll
        for (int jd = 0; jd < 8; jd++) {
            o[jd][0] *= sc0;  o[jd][1] *= sc0;
            o[jd][2] *= sc1;  o[jd][3] *= sc1;
        }
        __syncwarp();

        #pragma unroll
        for (int ks = 0; ks < 8; ks++) {
            uint32_t ap[4];
            int r0 = w*16 + gr;
            ap[0] = __float_as_uint(QPs[r0    ][8*ks + gc    ]);
            ap[1] = __float_as_uint(QPs[r0 + 8][8*ks + gc    ]);
            ap[2] = __float_as_uint(QPs[r0    ][8*ks + gc + 4]);
            ap[3] = __float_as_uint(QPs[r0 + 8][8*ks + gc + 4]);
            #pragma unroll
            for (int jd = 0; jd < 8; jd++) {
                uint32_t bv[2];
                bv[0] = __float_as_uint(Vs[8*ks + gc    ][jd*8 + gr]);
                bv[1] = __float_as_uint(Vs[8*ks + gc + 4][jd*8 + gr]);
                mma_tf32(o[jd], ap, bv);
            }
        }
        __syncthreads();
    }

    float i0 = 1.0f / l0, i1 = 1.0f / l1;
    #pragma unroll
    for (int jd = 0; jd < 8; jd++) {
        int d = jd*8 + gc*2;
        float* op = ctx + ((size_t)(b * S_ + rowg) * HID_ + h * D_ + d);
        *(float2*)op              = make_float2(o[jd][0] * i0, o[jd][1] * i0);
        *(float2*)(op + 8 * HID_) = make_float2(o[jd][2] * i1, o[jd][3] * i1);
    }
}

// ---------------------------------------------------------------------------
extern "C" void kernel_launch(void* const* d_in, const int* in_sizes, int n_in,
                              void* d_out, int out_size)
{
    const float* hid  = (const float*)d_in[0];
    const float* mask = (const float*)d_in[1];
    const float* Wq   = (const float*)d_in[2];
    const float* bq   = (const float*)d_in[3];
    const float* Wk   = (const float*)d_in[4];
    const float* bk   = (const float*)d_in[5];
    const float* Wv   = (const float*)d_in[6];
    const float* bv   = (const float*)d_in[7];
    float* out = (float*)d_out;

    // 0) prep: hidden -> fp16 hi plane; W -> fp16 (hi,lo) pairs
    split_prep<<<PREP_BLOCKS, 256>>>(hid, Wq, Wk, Wv);

    // 1) Q,K,V projections (fp16 2-term MMA, tf32-rounded outputs)
    qkv_mma<<<dim3(HID_ / 128, BS_ / 128, 3), 256>>>(bq, bk, bv);

    // 2) qq / kk / vv self-similarity scores
    scores_sim<<<dim3(S_ / 128, S_ / 64, 3 * BH_), 256>>>(mask, out + CTX_ELEMS);

    // 3) fused qk scores + softmax + P@V -> scores(qk) region + ctx
    flash_attn<<<dim3(S_ / 64, BH_), 128>>>(mask, out + CTX_ELEMS, out);
}